// round 2
// baseline (speedup 1.0000x reference)
#include <cuda_runtime.h>
#include <cuda_fp16.h>
#include <math.h>

#define Bn   256
#define IC   1152
#define En   8
#define NC   10
#define DV   16
#define JD   160     // NC*DV

// hat kernel tiling
#define HK_ICHUNK 32
#define HK_NCHUNK (IC / HK_ICHUNK)   // 36
#define HK_BTILE  64
#define HK_NBT    (Bn / HK_BTILE)    // 4

// routing pass kernel tiling
#define PK_ICHUNK 128
#define PK_NCHUNK (IC / PK_ICHUNK)   // 9

// Scratch (static device arrays; no cudaMalloc allowed)
__device__ __half g_hat[(size_t)Bn * IC * JD];            // 94.4 MB (fits in L2!)
__device__ float  g_Wt[(size_t)IC * JD * En];             // W transposed: [i][jd][e]
__device__ float  g_part0[(size_t)Bn * HK_NCHUNK * JD];   // pass-0 partials
__device__ float  g_part[(size_t)Bn * PK_NCHUNK * JD];    // pass-r partials
__device__ float  g_u[(size_t)Bn * JD];                   // v0 (+v1) running sum
__device__ int    g_cnt[2 * Bn];                          // zero-init; reset by winners

// ---------------------------------------------------------------------------
// Kernel 0: transpose W[i,j,e,d] -> Wt[i, jd, e]  (e contiguous -> float4 loads)
// ---------------------------------------------------------------------------
__global__ __launch_bounds__(256) void transpose_W(const float* __restrict__ W)
{
    const int i = blockIdx.x;
    const float* Wi = W + (size_t)i * (NC * En * DV);
    float* Wo = g_Wt + (size_t)i * (JD * En);
    for (int o = threadIdx.x; o < JD * En; o += 256) {
        const int e = o & 7, jd = o >> 3;
        const int j = jd >> 4, d = jd & 15;
        Wo[o] = __ldg(Wi + (j * En + e) * DV + d);
    }
}

// ---------------------------------------------------------------------------
// Kernel 1: hat[b,i,jd] = sum_e x[b,i,e]*Wt[i,jd,e]  -> fp16 store (stays in L2)
// plus fold pass-0 partial sums with c0 = softmax(bias[i,:]) (batch-independent).
// Grid (36, 4), 256 thr. Warp w owns 8 batches. Lane owns jd = lane + 32k, k<5.
// ---------------------------------------------------------------------------
__global__ __launch_bounds__(256) void hat_s0_kernel(
    const float* __restrict__ x,     // [B, IC, E]
    const float* __restrict__ bias)  // [1, IC, NC]
{
    const int chunk = blockIdx.x;          // 0..35
    const int bt    = blockIdx.y;          // 0..3
    const int tid   = threadIdx.x;
    const int w     = tid >> 5;
    const int lane  = tid & 31;
    const int i0    = chunk * HK_ICHUNK;
    const int b0    = bt * HK_BTILE + w * 8;   // this warp's first batch

    float acc[8][5];
#pragma unroll
    for (int bb = 0; bb < 8; bb++)
#pragma unroll
        for (int k = 0; k < 5; k++) acc[bb][k] = 0.f;

    for (int il = 0; il < HK_ICHUNK; il++) {
        const int i = i0 + il;

        // W slice: lane's 5 jd rows x 8 e, vectorized (2x float4 per row)
        float wv[5][8];
        const float4* wp = reinterpret_cast<const float4*>(g_Wt + (size_t)i * (JD * En));
#pragma unroll
        for (int k = 0; k < 5; k++) {
            const int jd = lane + 32 * k;
            const float4 a = __ldg(wp + jd * 2);
            const float4 c = __ldg(wp + jd * 2 + 1);
            wv[k][0]=a.x; wv[k][1]=a.y; wv[k][2]=a.z; wv[k][3]=a.w;
            wv[k][4]=c.x; wv[k][5]=c.y; wv[k][6]=c.z; wv[k][7]=c.w;
        }

        // c0 = softmax_j(bias[i,:]) (no max-sub: logits tiny)
        float c0[5];
        {
            float se = 0.f;
#pragma unroll
            for (int k = 0; k < 5; k++) {
                const int j = (lane >> 4) + 2 * k;
                c0[k] = __expf(__ldg(&bias[i * NC + j]));
                se += c0[k];
            }
            se += __shfl_xor_sync(0xffffffffu, se, 16);
            const float inv = __fdividef(1.f, se);
#pragma unroll
            for (int k = 0; k < 5; k++) c0[k] *= inv;
        }

        // 8 batches reuse the same W registers
#pragma unroll
        for (int bb = 0; bb < 8; bb++) {
            const int b = b0 + bb;
            const float4* xp =
                reinterpret_cast<const float4*>(x + ((size_t)b * IC + i) * En);
            const float4 x0 = __ldg(xp);
            const float4 x1 = __ldg(xp + 1);
            const float xv[8] = {x0.x, x0.y, x0.z, x0.w, x1.x, x1.y, x1.z, x1.w};

            __half* hp = g_hat + ((size_t)b * IC + i) * JD;
#pragma unroll
            for (int k = 0; k < 5; k++) {
                float s = 0.f;
#pragma unroll
                for (int e = 0; e < En; e++) s = fmaf(xv[e], wv[k][e], s);
                hp[lane + 32 * k] = __float2half_rn(s);
                acc[bb][k] = fmaf(c0[k], s, acc[bb][k]);
            }
        }
    }

#pragma unroll
    for (int bb = 0; bb < 8; bb++) {
        float* pp = g_part0 + ((size_t)(b0 + bb) * HK_NCHUNK + chunk) * JD;
#pragma unroll
        for (int k = 0; k < 5; k++) pp[lane + 32 * k] = acc[bb][k];
    }
}

// ---------------------------------------------------------------------------
// Kernel 2: routing pass over fp16 hat (L2-resident).
// MODE 1: u = v0 computed inline from g_part0; last block writes g_u = v0 + v1.
// MODE 2: u = g_u; last block writes output v2.
// Grid (9, 256), 256 thr. Warp w handles 16 i's.
// ---------------------------------------------------------------------------
template <int MODE>
__global__ __launch_bounds__(256) void pass_kernel(
    const float* __restrict__ bias, float* __restrict__ out)
{
    const int c    = blockIdx.x;   // 0..8
    const int b    = blockIdx.y;   // 0..255
    const int tid  = threadIdx.x;
    const int w    = tid >> 5;
    const int lane = tid & 31;

    __shared__ float us[JD];
    __shared__ float sred[8 * JD];
    __shared__ float sscale[NC];
    __shared__ int   sflag;

    if (MODE == 1) {
        // v0 = squash(sum over 36 chunks of part0)
        if (tid < JD) {
            float s = 0.f;
#pragma unroll
            for (int c2 = 0; c2 < HK_NCHUNK; c2++)
                s += g_part0[((size_t)b * HK_NCHUNK + c2) * JD + tid];
            sred[tid] = s;
        }
        __syncthreads();
        if (tid < NC) {
            float s2 = 0.f;
#pragma unroll
            for (int d = 0; d < DV; d++) { float v = sred[tid * DV + d]; s2 = fmaf(v, v, s2); }
            sscale[tid] = s2 / (1.0f + s2) * rsqrtf(s2);
        }
        __syncthreads();
        if (tid < JD) us[tid] = sscale[tid >> 4] * sred[tid];
    } else {
        if (tid < JD) us[tid] = g_u[(size_t)b * JD + tid];
    }
    __syncthreads();

    float u[5];
#pragma unroll
    for (int k = 0; k < 5; k++) u[k] = us[lane + 32 * k];

    float acc[5] = {0.f, 0.f, 0.f, 0.f, 0.f};
    const int i0 = c * PK_ICHUNK + w * 16;
    const __half* hp0 = g_hat + ((size_t)b * IC + i0) * JD;

#pragma unroll 4
    for (int t = 0; t < 16; t++) {
        const __half* hp = hp0 + (size_t)t * JD;
        float h[5], p[5];
#pragma unroll
        for (int k = 0; k < 5; k++) h[k] = __half2float(__ldg(hp + lane + 32 * k));
#pragma unroll
        for (int k = 0; k < 5; k++) p[k] = h[k] * u[k];

        // reduce over d (16 lanes per j)
#pragma unroll
        for (int off = 1; off < 16; off <<= 1)
#pragma unroll
            for (int k = 0; k < 5; k++)
                p[k] += __shfl_xor_sync(0xffffffffu, p[k], off);

        const int i = i0 + t;
        float se = 0.f;
#pragma unroll
        for (int k = 0; k < 5; k++) {
            const int j = (lane >> 4) + 2 * k;
            p[k] = __expf(p[k] + __ldg(&bias[i * NC + j]));   // no max-sub: logits bounded
            se += p[k];
        }
        se += __shfl_xor_sync(0xffffffffu, se, 16);
        const float inv = __fdividef(1.f, se);
#pragma unroll
        for (int k = 0; k < 5; k++) acc[k] = fmaf(p[k] * inv, h[k], acc[k]);
    }

#pragma unroll
    for (int k = 0; k < 5; k++) sred[w * JD + lane + 32 * k] = acc[k];
    __syncthreads();

    if (tid < JD) {
        float s = 0.f;
#pragma unroll
        for (int w2 = 0; w2 < 8; w2++) s += sred[w2 * JD + tid];
        g_part[((size_t)b * PK_NCHUNK + c) * JD + tid] = s;
    }
    __syncthreads();

    // last-block-per-b: reduce partials, squash, publish (deterministic: fixed sum order)
    if (tid == 0) {
        __threadfence();
        int* cnt = &g_cnt[(MODE - 1) * Bn + b];
        const int old = atomicAdd(cnt, 1);
        sflag = (old == PK_NCHUNK - 1);
        if (old == PK_NCHUNK - 1) *cnt = 0;   // reset for next replay
    }
    __syncthreads();

    if (sflag) {
        __threadfence();
        if (tid < JD) {
            float s = 0.f;
#pragma unroll
            for (int c2 = 0; c2 < PK_NCHUNK; c2++)
                s += g_part[((size_t)b * PK_NCHUNK + c2) * JD + tid];
            sred[tid] = s;
        }
        __syncthreads();
        if (tid < NC) {
            float s2 = 0.f;
#pragma unroll
            for (int d = 0; d < DV; d++) { float v = sred[tid * DV + d]; s2 = fmaf(v, v, s2); }
            sscale[tid] = s2 / (1.0f + s2) * rsqrtf(s2);
        }
        __syncthreads();
        if (tid < JD) {
            const float v = sscale[tid >> 4] * sred[tid];
            if (MODE == 1) g_u[(size_t)b * JD + tid] = us[tid] + v;   // u = v0 + v1
            else           out[(size_t)b * JD + tid] = v;             // output v2
        }
    }
}

// ---------------------------------------------------------------------------
extern "C" void kernel_launch(void* const* d_in, const int* in_sizes, int n_in,
                              void* d_out, int out_size)
{
    const float* x    = (const float*)d_in[0];   // [256,1152,8]
    const float* W    = (const float*)d_in[1];   // [1152,10,8,16]
    const float* bias = (const float*)d_in[2];   // [1,1152,10]
    float* out        = (float*)d_out;           // [256,10,16]

    transpose_W<<<IC, 256>>>(W);
    hat_s0_kernel<<<dim3(HK_NCHUNK, HK_NBT), 256>>>(x, bias);
    pass_kernel<1><<<dim3(PK_NCHUNK, Bn), 256>>>(bias, out);
    pass_kernel<2><<<dim3(PK_NCHUNK, Bn), 256>>>(bias, out);
}

// round 3
// speedup vs baseline: 1.4268x; 1.4268x over previous
#include <cuda_runtime.h>
#include <cuda_fp16.h>
#include <math.h>

#define Bn   256
#define IC   1152
#define En   8
#define NC   10
#define DV   16
#define JD   160     // NC*DV

// hat kernel tiling
#define HK_ICHUNK 32
#define HK_NCHUNK (IC / HK_ICHUNK)   // 36
#define HK_BTILE  32
#define HK_NBT    (Bn / HK_BTILE)    // 8

// routing kernel
#define RT_THREADS 384
#define RT_WARPS   12
#define RT_ISTRIPE (IC / RT_WARPS)   // 96

// Scratch (static device arrays; no cudaMalloc allowed)
__device__ __half g_hat[(size_t)Bn * IC * JD];            // 94.4 MB (L2-resident)
__device__ float  g_Wt[(size_t)IC * JD * En];             // W transposed: [i][jd][e]
__device__ float  g_part0[(size_t)Bn * HK_NCHUNK * JD];   // pass-0 partials

// ---------------------------------------------------------------------------
// Kernel 0: transpose W[i,j,e,d] -> Wt[i, jd, e]  (e contiguous -> float4 loads)
// ---------------------------------------------------------------------------
__global__ __launch_bounds__(256) void transpose_W(const float* __restrict__ W)
{
    const int i = blockIdx.x;
    const float* Wi = W + (size_t)i * (NC * En * DV);
    float* Wo = g_Wt + (size_t)i * (JD * En);
    for (int o = threadIdx.x; o < JD * En; o += 256) {
        const int e = o & 7, jd = o >> 3;
        const int j = jd >> 4, d = jd & 15;
        Wo[o] = __ldg(Wi + (j * En + e) * DV + d);
    }
}

// ---------------------------------------------------------------------------
// Kernel 1: hat[b,i,jd] = sum_e x[b,i,e]*Wt[i,jd,e] -> fp16 store (stays in L2)
// plus pass-0 partials with c0 = softmax(bias[i,:]) (batch-independent).
// Grid (36, 8), 256 thr. Warp w owns 4 batches. Lane owns jd = lane + 32k, k<5.
// ---------------------------------------------------------------------------
__global__ __launch_bounds__(256, 2) void hat_s0_kernel(
    const float* __restrict__ x,     // [B, IC, E]
    const float* __restrict__ bias)  // [1, IC, NC]
{
    const int chunk = blockIdx.x;          // 0..35
    const int bt    = blockIdx.y;          // 0..7
    const int tid   = threadIdx.x;
    const int w     = tid >> 5;
    const int lane  = tid & 31;
    const int i0    = chunk * HK_ICHUNK;
    const int b0    = bt * HK_BTILE + w * 4;   // this warp's first batch

    float acc[4][5];
#pragma unroll
    for (int bb = 0; bb < 4; bb++)
#pragma unroll
        for (int k = 0; k < 5; k++) acc[bb][k] = 0.f;

    for (int il = 0; il < HK_ICHUNK; il++) {
        const int i = i0 + il;

        // W slice: lane's 5 jd rows x 8 e (2x float4 per row)
        float wv[5][8];
        const float4* wp = reinterpret_cast<const float4*>(g_Wt + (size_t)i * (JD * En));
#pragma unroll
        for (int k = 0; k < 5; k++) {
            const int jd = lane + 32 * k;
            const float4 a = __ldg(wp + jd * 2);
            const float4 c = __ldg(wp + jd * 2 + 1);
            wv[k][0]=a.x; wv[k][1]=a.y; wv[k][2]=a.z; wv[k][3]=a.w;
            wv[k][4]=c.x; wv[k][5]=c.y; wv[k][6]=c.z; wv[k][7]=c.w;
        }

        // c0 = softmax_j(bias[i,:]) (logits tiny: no max-sub)
        float c0[5];
        {
            float se = 0.f;
#pragma unroll
            for (int k = 0; k < 5; k++) {
                const int j = (lane >> 4) + 2 * k;
                c0[k] = __expf(__ldg(&bias[i * NC + j]));
                se += c0[k];
            }
            se += __shfl_xor_sync(0xffffffffu, se, 16);
            const float inv = __fdividef(1.f, se);
#pragma unroll
            for (int k = 0; k < 5; k++) c0[k] *= inv;
        }

#pragma unroll
        for (int bb = 0; bb < 4; bb++) {
            const int b = b0 + bb;
            const float4* xp =
                reinterpret_cast<const float4*>(x + ((size_t)b * IC + i) * En);
            const float4 x0 = __ldg(xp);
            const float4 x1 = __ldg(xp + 1);
            const float xv[8] = {x0.x, x0.y, x0.z, x0.w, x1.x, x1.y, x1.z, x1.w};

            __half* hp = g_hat + ((size_t)b * IC + i) * JD;
#pragma unroll
            for (int k = 0; k < 5; k++) {
                float s = 0.f;
#pragma unroll
                for (int e = 0; e < En; e++) s = fmaf(xv[e], wv[k][e], s);
                hp[lane + 32 * k] = __float2half_rn(s);
                acc[bb][k] = fmaf(c0[k], s, acc[bb][k]);
            }
        }
    }

#pragma unroll
    for (int bb = 0; bb < 4; bb++) {
        float* pp = g_part0 + ((size_t)(b0 + bb) * HK_NCHUNK + chunk) * JD;
#pragma unroll
        for (int k = 0; k < 5; k++) pp[lane + 32 * k] = acc[bb][k];
    }
}

// ---------------------------------------------------------------------------
// Kernel 2: ALL routing for one b in one block (grid 256, 384 threads).
// v0 from g_part0; then 2 passes, each:
//   Phase A: thread-per-i agreement (half2 FMA vs u in smem) + in-register
//            softmax -> c_sm (fp16, 23KB). Zero shuffles.
//   Phase B: lane-owns-jd streaming weighted sum (5 LDG + 5 LDS + 5 FFMA / i).
//   In-block reduce + squash; u telescopes (logits_r = bias + <hat, sum v>).
// ---------------------------------------------------------------------------
__global__ __launch_bounds__(RT_THREADS, 2) void route_kernel(
    const float* __restrict__ bias, float* __restrict__ out)
{
    const int b    = blockIdx.x;
    const int tid  = threadIdx.x;
    const int w    = tid >> 5;
    const int lane = tid & 31;

    __shared__ __align__(16) __half uh[JD];     // u as fp16 (for half2 agreement)
    __shared__ __half c_sm[IC * NC];            // coupling coeffs (23040 B)
    __shared__ float  sred[RT_WARPS * JD];      // per-warp partials (7680 B)
    __shared__ float  s_sm[JD];
    __shared__ float  u_f[JD];                  // running sum of v (fp32)
    __shared__ float  scale_sm[NC];

    // ---- v0 = squash(sum of pass-0 partials) ----
    if (tid < JD) {
        float s = 0.f;
#pragma unroll
        for (int c = 0; c < HK_NCHUNK; c++)
            s += g_part0[((size_t)b * HK_NCHUNK + c) * JD + tid];
        s_sm[tid] = s;
    }
    __syncthreads();
    if (tid < NC) {
        float s2 = 0.f;
#pragma unroll
        for (int d = 0; d < DV; d++) { float v = s_sm[tid * DV + d]; s2 = fmaf(v, v, s2); }
        scale_sm[tid] = s2 / (1.0f + s2) * rsqrtf(s2);
    }
    __syncthreads();
    if (tid < JD) {
        const float v = scale_sm[tid >> 4] * s_sm[tid];
        u_f[tid] = v;
        uh[tid]  = __float2half_rn(v);
    }
    __syncthreads();

    for (int pass = 0; pass < 2; pass++) {
        // ===== Phase A: agreement + softmax, one i per thread =====
        const __half2* u2 = reinterpret_cast<const __half2*>(uh);
        for (int it = 0; it < IC / RT_THREADS; it++) {
            const int i = it * RT_THREADS + tid;
            const uint4* hp =
                reinterpret_cast<const uint4*>(g_hat + ((size_t)b * IC + i) * JD);
            float a[NC];
#pragma unroll
            for (int j = 0; j < NC; j++) {
                const uint4 q0 = __ldg(hp + 2 * j);
                const uint4 q1 = __ldg(hp + 2 * j + 1);
                const __half2* h2a = reinterpret_cast<const __half2*>(&q0);
                const __half2* h2b = reinterpret_cast<const __half2*>(&q1);
                __half2 acc2 = __float2half2_rn(0.f);
#pragma unroll
                for (int m = 0; m < 4; m++) acc2 = __hfma2(h2a[m], u2[j * 8 + m], acc2);
#pragma unroll
                for (int m = 0; m < 4; m++) acc2 = __hfma2(h2b[m], u2[j * 8 + 4 + m], acc2);
                a[j] = __low2float(acc2) + __high2float(acc2) + __ldg(&bias[i * NC + j]);
            }
            float se = 0.f;
#pragma unroll
            for (int j = 0; j < NC; j++) { a[j] = __expf(a[j]); se += a[j]; }
            const float inv = __fdividef(1.f, se);
#pragma unroll
            for (int j = 0; j < NC; j++)
                c_sm[i * NC + j] = __float2half_rn(a[j] * inv);
        }
        __syncthreads();

        // ===== Phase B: weighted sum, lane-owns-jd streaming =====
        float acc[5] = {0.f, 0.f, 0.f, 0.f, 0.f};
        const int i0 = w * RT_ISTRIPE;
        const __half* hbase = g_hat + ((size_t)b * IC + i0) * JD;
#pragma unroll 4
        for (int t = 0; t < RT_ISTRIPE; t++) {
            const __half* hp = hbase + (size_t)t * JD;
            const int ci = (i0 + t) * NC;
#pragma unroll
            for (int k = 0; k < 5; k++) {
                const int jd = lane + 32 * k;
                const float h = __half2float(__ldg(hp + jd));
                const float c = __half2float(c_sm[ci + (jd >> 4)]);
                acc[k] = fmaf(c, h, acc[k]);
            }
        }
#pragma unroll
        for (int k = 0; k < 5; k++) sred[w * JD + lane + 32 * k] = acc[k];
        __syncthreads();

        // ===== reduce + squash =====
        if (tid < JD) {
            float s = 0.f;
#pragma unroll
            for (int w2 = 0; w2 < RT_WARPS; w2++) s += sred[w2 * JD + tid];
            s_sm[tid] = s;
        }
        __syncthreads();
        if (tid < NC) {
            float s2 = 0.f;
#pragma unroll
            for (int d = 0; d < DV; d++) { float v = s_sm[tid * DV + d]; s2 = fmaf(v, v, s2); }
            scale_sm[tid] = s2 / (1.0f + s2) * rsqrtf(s2);
        }
        __syncthreads();
        if (tid < JD) {
            const float v = scale_sm[tid >> 4] * s_sm[tid];
            if (pass == 0) {
                const float un = u_f[tid] + v;   // logits telescope: u = v0 + v1
                u_f[tid] = un;
                uh[tid]  = __float2half_rn(un);
            } else {
                out[(size_t)b * JD + tid] = v;   // final output v2
            }
        }
        __syncthreads();
    }
}

// ---------------------------------------------------------------------------
extern "C" void kernel_launch(void* const* d_in, const int* in_sizes, int n_in,
                              void* d_out, int out_size)
{
    const float* x    = (const float*)d_in[0];   // [256,1152,8]
    const float* W    = (const float*)d_in[1];   // [1152,10,8,16]
    const float* bias = (const float*)d_in[2];   // [1,1152,10]
    float* out        = (float*)d_out;           // [256,10,16]

    transpose_W<<<IC, 256>>>(W);
    hat_s0_kernel<<<dim3(HK_NCHUNK, HK_NBT), 256>>>(x, bias);
    route_kernel<<<Bn, RT_THREADS>>>(bias, out);
}

// round 4
// speedup vs baseline: 1.5484x; 1.0853x over previous
#include <cuda_runtime.h>
#include <cuda_fp16.h>
#include <math.h>

#define Bn   256
#define IC   1152
#define En   8
#define NC   10
#define DV   16
#define JD   160     // NC*DV

// hat kernel tiling
#define HK_ICHUNK 32
#define HK_NCHUNK (IC / HK_ICHUNK)   // 36
#define HK_BTILE  32
#define HK_NBT    (Bn / HK_BTILE)    // 8

// routing kernel
#define RT_THREADS 384
#define RT_WARPS   12
#define CH         192               // i-chunk staged in smem
#define NCHUNKS    (IC / CH)         // 6
#define ROWU4      21                // uint4 per padded smem row (336B)
#define ROWH       168               // halves per padded smem row
#define SMH_BYTES  (CH * ROWU4 * 16) // 64512

// Scratch (static device arrays; no cudaMalloc allowed)
__device__ __half g_hat[(size_t)Bn * IC * JD];            // 94.4 MB (L2-resident)
__device__ float  g_Wt[(size_t)IC * JD * En];             // W transposed: [i][jd][e]
__device__ float  g_part0[(size_t)Bn * HK_NCHUNK * JD];   // pass-0 partials

// ---------------------------------------------------------------------------
// Kernel 0: transpose W[i,j,e,d] -> Wt[i, jd, e], smem-tiled (coalesced both sides)
// ---------------------------------------------------------------------------
__global__ __launch_bounds__(128) void transpose_W(const float* __restrict__ W)
{
    const int i = blockIdx.x;
    __shared__ float sw[1280 + 80];            // pad 1 word per 16
    const float* Wi = W + (size_t)i * (NC * En * DV);
#pragma unroll
    for (int o = threadIdx.x; o < NC * En * DV; o += 128)
        sw[o + (o >> 4)] = __ldg(Wi + o);
    __syncthreads();
    float* Wo = g_Wt + (size_t)i * (JD * En);
#pragma unroll
    for (int o = threadIdx.x; o < JD * En; o += 128) {
        const int e = o & 7, jd = o >> 3;
        const int src = (jd >> 4) * (En * DV) + e * DV + (jd & 15);
        Wo[o] = sw[src + (src >> 4)];
    }
}

// ---------------------------------------------------------------------------
// Kernel 1: hat[b,i,jd] = sum_e x[b,i,e]*Wt[i,jd,e] -> fp16 store (stays in L2)
// plus pass-0 partials with c0 = softmax(bias[i,:]) (batch-independent).
// ---------------------------------------------------------------------------
__global__ __launch_bounds__(256, 2) void hat_s0_kernel(
    const float* __restrict__ x,     // [B, IC, E]
    const float* __restrict__ bias)  // [1, IC, NC]
{
    const int chunk = blockIdx.x;          // 0..35
    const int bt    = blockIdx.y;          // 0..7
    const int tid   = threadIdx.x;
    const int w     = tid >> 5;
    const int lane  = tid & 31;
    const int i0    = chunk * HK_ICHUNK;
    const int b0    = bt * HK_BTILE + w * 4;

    float acc[4][5];
#pragma unroll
    for (int bb = 0; bb < 4; bb++)
#pragma unroll
        for (int k = 0; k < 5; k++) acc[bb][k] = 0.f;

    for (int il = 0; il < HK_ICHUNK; il++) {
        const int i = i0 + il;

        float wv[5][8];
        const float4* wp = reinterpret_cast<const float4*>(g_Wt + (size_t)i * (JD * En));
#pragma unroll
        for (int k = 0; k < 5; k++) {
            const int jd = lane + 32 * k;
            const float4 a = __ldg(wp + jd * 2);
            const float4 c = __ldg(wp + jd * 2 + 1);
            wv[k][0]=a.x; wv[k][1]=a.y; wv[k][2]=a.z; wv[k][3]=a.w;
            wv[k][4]=c.x; wv[k][5]=c.y; wv[k][6]=c.z; wv[k][7]=c.w;
        }

        float c0[5];
        {
            float se = 0.f;
#pragma unroll
            for (int k = 0; k < 5; k++) {
                const int j = (lane >> 4) + 2 * k;
                c0[k] = __expf(__ldg(&bias[i * NC + j]));
                se += c0[k];
            }
            se += __shfl_xor_sync(0xffffffffu, se, 16);
            const float inv = __fdividef(1.f, se);
#pragma unroll
            for (int k = 0; k < 5; k++) c0[k] *= inv;
        }

#pragma unroll
        for (int bb = 0; bb < 4; bb++) {
            const int b = b0 + bb;
            const float4* xp =
                reinterpret_cast<const float4*>(x + ((size_t)b * IC + i) * En);
            const float4 x0 = __ldg(xp);
            const float4 x1 = __ldg(xp + 1);
            const float xv[8] = {x0.x, x0.y, x0.z, x0.w, x1.x, x1.y, x1.z, x1.w};

            __half* hp = g_hat + ((size_t)b * IC + i) * JD;
#pragma unroll
            for (int k = 0; k < 5; k++) {
                float s = 0.f;
#pragma unroll
                for (int e = 0; e < En; e++) s = fmaf(xv[e], wv[k][e], s);
                hp[lane + 32 * k] = __float2half_rn(s);
                acc[bb][k] = fmaf(c0[k], s, acc[bb][k]);
            }
        }
    }

#pragma unroll
    for (int bb = 0; bb < 4; bb++) {
        float* pp = g_part0 + ((size_t)(b0 + bb) * HK_NCHUNK + chunk) * JD;
#pragma unroll
        for (int k = 0; k < 5; k++) pp[lane + 32 * k] = acc[bb][k];
    }
}

// ---------------------------------------------------------------------------
// Kernel 2: all routing for one b (grid 256, 384 thr). Per pass, per 192-i
// chunk: coalesced load hat slice -> smem (padded rows), Phase A (thread-per-i
// agreement+softmax from smem, conflict-free LDS.128), Phase B (lane-owns-jd
// weighted sum from smem, fp32). Reduce + squash per pass; u telescopes.
// ---------------------------------------------------------------------------
extern __shared__ __half smh[];   // CH rows x ROWH halves (padded)

__global__ __launch_bounds__(RT_THREADS, 2) void route_kernel(
    const float* __restrict__ bias, float* __restrict__ out)
{
    __shared__ float bias_s[CH * NC];
    __shared__ float c_f[CH * NC];
    __shared__ float sred[RT_WARPS * JD];
    __shared__ float s_sm[JD], u_f[JD], scale_sm[NC];
    __shared__ __align__(16) __half2 us2[JD / 2];

    const int b    = blockIdx.x;
    const int tid  = threadIdx.x;
    const int w    = tid >> 5;
    const int lane = tid & 31;

    // ---- v0 = squash(sum of pass-0 partials) ----
    if (tid < JD) {
        float s = 0.f;
#pragma unroll
        for (int c = 0; c < HK_NCHUNK; c++)
            s += g_part0[((size_t)b * HK_NCHUNK + c) * JD + tid];
        s_sm[tid] = s;
    }
    __syncthreads();
    if (tid < NC) {
        float s2 = 0.f;
#pragma unroll
        for (int d = 0; d < DV; d++) { float v = s_sm[tid * DV + d]; s2 = fmaf(v, v, s2); }
        scale_sm[tid] = s2 / (1.0f + s2) * rsqrtf(s2);
    }
    __syncthreads();
    if (tid < JD) u_f[tid] = scale_sm[tid >> 4] * s_sm[tid];
    __syncthreads();
    if (tid < JD / 2) us2[tid] = __floats2half2_rn(u_f[2 * tid], u_f[2 * tid + 1]);
    __syncthreads();

    for (int pass = 0; pass < 2; pass++) {
        float acc[5] = {0.f, 0.f, 0.f, 0.f, 0.f};

        for (int ch = 0; ch < NCHUNKS; ch++) {
            const int i0 = ch * CH;

            // ---- coalesced load: hat chunk (contiguous 60KB) + bias chunk ----
            {
                const uint4* src =
                    reinterpret_cast<const uint4*>(g_hat + ((size_t)b * IC + i0) * JD);
                uint4* dst = reinterpret_cast<uint4*>(smh);
#pragma unroll
                for (int q = tid; q < CH * 20; q += RT_THREADS)
                    dst[q + q / 20] = __ldg(src + q);   // +r pad per row (21 u4/row)
                for (int o = tid; o < CH * NC; o += RT_THREADS)
                    bias_s[o] = __ldg(bias + i0 * NC + o);
            }
            __syncthreads();

            // ---- Phase A: agreement + softmax, thread-per-i from smem ----
            if (tid < CH) {
                const uint4* row = reinterpret_cast<const uint4*>(smh) + tid * ROWU4;
                float a[NC];
                float se = 0.f;
#pragma unroll
                for (int j = 0; j < NC; j++) {
                    const uint4 q0 = row[2 * j];
                    const uint4 q1 = row[2 * j + 1];
                    const __half2* ha = reinterpret_cast<const __half2*>(&q0);
                    const __half2* hb = reinterpret_cast<const __half2*>(&q1);
                    __half2 a2 = __float2half2_rn(0.f);
#pragma unroll
                    for (int m = 0; m < 4; m++) a2 = __hfma2(ha[m], us2[j * 8 + m], a2);
#pragma unroll
                    for (int m = 0; m < 4; m++) a2 = __hfma2(hb[m], us2[j * 8 + 4 + m], a2);
                    a[j] = __expf(__low2float(a2) + __high2float(a2) +
                                  bias_s[tid * NC + j]);
                    se += a[j];
                }
                const float inv = __fdividef(1.f, se);
#pragma unroll
                for (int j = 0; j < NC; j++) c_f[tid * NC + j] = a[j] * inv;
            }
            __syncthreads();

            // ---- Phase B: weighted sum, lane-owns-jd from smem (fp32) ----
            {
                const __half* hb0 = smh + (size_t)(w * 16) * ROWH;
                const float*  cb0 = c_f + (w * 16) * NC;
#pragma unroll 4
                for (int t = 0; t < 16; t++) {
                    const __half* hp = hb0 + (size_t)t * ROWH;
                    const float*  cp = cb0 + t * NC;
#pragma unroll
                    for (int k = 0; k < 5; k++) {
                        const int jd = lane + 32 * k;
                        acc[k] = fmaf(cp[jd >> 4], __half2float(hp[jd]), acc[k]);
                    }
                }
            }
            __syncthreads();   // smh/c_f consumed; safe to overwrite next chunk
        }

        // ---- reduce + squash ----
#pragma unroll
        for (int k = 0; k < 5; k++) sred[w * JD + lane + 32 * k] = acc[k];
        __syncthreads();
        if (tid < JD) {
            float s = 0.f;
#pragma unroll
            for (int w2 = 0; w2 < RT_WARPS; w2++) s += sred[w2 * JD + tid];
            s_sm[tid] = s;
        }
        __syncthreads();
        if (tid < NC) {
            float s2 = 0.f;
#pragma unroll
            for (int d = 0; d < DV; d++) { float v = s_sm[tid * DV + d]; s2 = fmaf(v, v, s2); }
            scale_sm[tid] = s2 / (1.0f + s2) * rsqrtf(s2);
        }
        __syncthreads();
        if (tid < JD) {
            const float v = scale_sm[tid >> 4] * s_sm[tid];
            if (pass == 0) u_f[tid] += v;                 // u = v0 + v1 (telescoped)
            else           out[(size_t)b * JD + tid] = v; // final output v2
        }
        __syncthreads();
        if (pass == 0 && tid < JD / 2)
            us2[tid] = __floats2half2_rn(u_f[2 * tid], u_f[2 * tid + 1]);
        __syncthreads();
    }
}

// ---------------------------------------------------------------------------
extern "C" void kernel_launch(void* const* d_in, const int* in_sizes, int n_in,
                              void* d_out, int out_size)
{
    const float* x    = (const float*)d_in[0];   // [256,1152,8]
    const float* W    = (const float*)d_in[1];   // [1152,10,8,16]
    const float* bias = (const float*)d_in[2];   // [1,1152,10]
    float* out        = (float*)d_out;           // [256,10,16]

    cudaFuncSetAttribute(route_kernel,
                         cudaFuncAttributeMaxDynamicSharedMemorySize, SMH_BYTES);

    transpose_W<<<IC, 128>>>(W);
    hat_s0_kernel<<<dim3(HK_NCHUNK, HK_NBT), 256>>>(x, bias);
    route_kernel<<<Bn, RT_THREADS, SMH_BYTES>>>(bias, out);
}

// round 5
// speedup vs baseline: 1.6847x; 1.0880x over previous
#include <cuda_runtime.h>
#include <cuda_fp16.h>
#include <cuda_pipeline.h>
#include <math.h>

#define Bn   256
#define IC   1152
#define En   8
#define NC   10
#define DV   16
#define JD   160     // NC*DV

// hat kernel tiling
#define HK_ICHUNK 32
#define HK_NCHUNK (IC / HK_ICHUNK)   // 36
#define HK_BTILE  32
#define HK_NBT    (Bn / HK_BTILE)    // 8

// routing kernel
#define RT_THREADS 384
#define RT_WARPS   12
#define CH         96                // i-chunk staged in smem
#define NCHUNKS    (IC / CH)         // 12
#define ROWU4      21                // uint4 per padded smem row (336B)
#define ROWH       168               // halves per padded row
#define U4_PER_BUF (CH * ROWU4)      // 2016
#define SMH_BYTES  (2 * U4_PER_BUF * 16)  // 64512 (double buffered)

// Scratch (static device arrays; no cudaMalloc allowed)
__device__ __half g_hat[(size_t)Bn * IC * JD];            // 94.4 MB (L2-resident)
__device__ float  g_Wt[(size_t)IC * JD * En];             // W transposed: [i][jd][e]
__device__ float  g_part0[(size_t)Bn * HK_NCHUNK * JD];   // pass-0 partials

// ---------------------------------------------------------------------------
// Kernel 0: transpose W[i,j,e,d] -> Wt[i, jd, e], smem-tiled
// ---------------------------------------------------------------------------
__global__ __launch_bounds__(128) void transpose_W(const float* __restrict__ W)
{
    const int i = blockIdx.x;
    __shared__ float sw[1280 + 80];
    const float* Wi = W + (size_t)i * (NC * En * DV);
#pragma unroll
    for (int o = threadIdx.x; o < NC * En * DV; o += 128)
        sw[o + (o >> 4)] = __ldg(Wi + o);
    __syncthreads();
    float* Wo = g_Wt + (size_t)i * (JD * En);
#pragma unroll
    for (int o = threadIdx.x; o < JD * En; o += 128) {
        const int e = o & 7, jd = o >> 3;
        const int src = (jd >> 4) * (En * DV) + e * DV + (jd & 15);
        Wo[o] = sw[src + (src >> 4)];
    }
}

// ---------------------------------------------------------------------------
// Kernel 1: hat[b,i,jd] = sum_e x[b,i,e]*Wt[i,jd,e] -> fp16 (L2-resident)
// plus pass-0 partials with c0 = softmax(bias[i,:]) (batch-independent).
// ---------------------------------------------------------------------------
__global__ __launch_bounds__(256, 2) void hat_s0_kernel(
    const float* __restrict__ x, const float* __restrict__ bias)
{
    const int chunk = blockIdx.x;
    const int bt    = blockIdx.y;
    const int tid   = threadIdx.x;
    const int w     = tid >> 5;
    const int lane  = tid & 31;
    const int i0    = chunk * HK_ICHUNK;
    const int b0    = bt * HK_BTILE + w * 4;

    float acc[4][5];
#pragma unroll
    for (int bb = 0; bb < 4; bb++)
#pragma unroll
        for (int k = 0; k < 5; k++) acc[bb][k] = 0.f;

    for (int il = 0; il < HK_ICHUNK; il++) {
        const int i = i0 + il;

        float wv[5][8];
        const float4* wp = reinterpret_cast<const float4*>(g_Wt + (size_t)i * (JD * En));
#pragma unroll
        for (int k = 0; k < 5; k++) {
            const int jd = lane + 32 * k;
            const float4 a = __ldg(wp + jd * 2);
            const float4 c = __ldg(wp + jd * 2 + 1);
            wv[k][0]=a.x; wv[k][1]=a.y; wv[k][2]=a.z; wv[k][3]=a.w;
            wv[k][4]=c.x; wv[k][5]=c.y; wv[k][6]=c.z; wv[k][7]=c.w;
        }

        float c0[5];
        {
            float se = 0.f;
#pragma unroll
            for (int k = 0; k < 5; k++) {
                const int j = (lane >> 4) + 2 * k;
                c0[k] = __expf(__ldg(&bias[i * NC + j]));
                se += c0[k];
            }
            se += __shfl_xor_sync(0xffffffffu, se, 16);
            const float inv = __fdividef(1.f, se);
#pragma unroll
            for (int k = 0; k < 5; k++) c0[k] *= inv;
        }

#pragma unroll
        for (int bb = 0; bb < 4; bb++) {
            const int b = b0 + bb;
            const float4* xp =
                reinterpret_cast<const float4*>(x + ((size_t)b * IC + i) * En);
            const float4 x0 = __ldg(xp);
            const float4 x1 = __ldg(xp + 1);
            const float xv[8] = {x0.x, x0.y, x0.z, x0.w, x1.x, x1.y, x1.z, x1.w};

            __half* hp = g_hat + ((size_t)b * IC + i) * JD;
#pragma unroll
            for (int k = 0; k < 5; k++) {
                float s = 0.f;
#pragma unroll
                for (int e = 0; e < En; e++) s = fmaf(xv[e], wv[k][e], s);
                hp[lane + 32 * k] = __float2half_rn(s);
                acc[bb][k] = fmaf(c0[k], s, acc[bb][k]);
            }
        }
    }

#pragma unroll
    for (int bb = 0; bb < 4; bb++) {
        float* pp = g_part0 + ((size_t)(b0 + bb) * HK_NCHUNK + chunk) * JD;
#pragma unroll
        for (int k = 0; k < 5; k++) pp[lane + 32 * k] = acc[bb][k];
    }
}

// ---------------------------------------------------------------------------
// Kernel 2: all routing for one b. Double-buffered cp.async chunk loads
// (CH=96) overlap with compute. Phase A: quad-per-i (all 384 threads).
// Phase B: lane-owns-jd weighted sum. Squash per pass; u telescopes.
// ---------------------------------------------------------------------------
extern __shared__ uint4 smu4[];   // 2 buffers x CH x 21 uint4

__device__ __forceinline__ void load_chunk(int b, int ch, int buf, int tid)
{
    const uint4* src =
        reinterpret_cast<const uint4*>(g_hat + ((size_t)b * IC + ch * CH) * JD);
    uint4* dst = smu4 + buf * U4_PER_BUF;
#pragma unroll
    for (int k = 0; k < 5; k++) {                 // 5*384 = 1920 = CH*20 exactly
        const int q = tid + k * RT_THREADS;
        const int row = q / 20, col = q % 20;
        __pipeline_memcpy_async(dst + row * ROWU4 + col, src + q, 16);
    }
    __pipeline_commit();
}

__global__ __launch_bounds__(RT_THREADS, 2) void route_kernel(
    const float* __restrict__ bias, float* __restrict__ out)
{
    __shared__ float c_f[CH * NC];               // 3.84 KB
    __shared__ float sred[RT_WARPS * JD];        // 7.68 KB
    __shared__ float s_sm[JD], u_f[JD], scale_sm[NC];
    __shared__ __align__(16) __half2 us2[JD / 2];

    const int b    = blockIdx.x;
    const int tid  = threadIdx.x;
    const int w    = tid >> 5;
    const int lane = tid & 31;
    const int quad = tid >> 2;       // 0..95 == i within chunk
    const int g    = tid & 3;
    const int jn   = (g < 2) ? 3 : 2;

    load_chunk(b, 0, 0, tid);        // prefetch pass-0 chunk 0 behind v0 compute

    // ---- v0 = squash(sum of pass-0 partials) ----
    if (tid < JD) {
        float s = 0.f;
#pragma unroll
        for (int c = 0; c < HK_NCHUNK; c++)
            s += g_part0[((size_t)b * HK_NCHUNK + c) * JD + tid];
        s_sm[tid] = s;
    }
    __syncthreads();
    if (tid < NC) {
        float s2 = 0.f;
#pragma unroll
        for (int d = 0; d < DV; d++) { float v = s_sm[tid * DV + d]; s2 = fmaf(v, v, s2); }
        scale_sm[tid] = s2 / (1.0f + s2) * rsqrtf(s2);
    }
    __syncthreads();
    if (tid < JD) u_f[tid] = scale_sm[tid >> 4] * s_sm[tid];
    __syncthreads();
    if (tid < JD / 2) us2[tid] = __floats2half2_rn(u_f[2 * tid], u_f[2 * tid + 1]);
    __syncthreads();

    for (int pass = 0; pass < 2; pass++) {
        float acc[5] = {0.f, 0.f, 0.f, 0.f, 0.f};

        for (int ch = 0; ch < NCHUNKS; ch++) {
            const int buf = ch & 1;
            if (ch + 1 < NCHUNKS) {
                load_chunk(b, ch + 1, (ch + 1) & 1, tid);
                __pipeline_wait_prior(1);
            } else {
                __pipeline_wait_prior(0);
            }
            __syncthreads();

            // ---- Phase A: quad-per-i agreement + softmax (all threads) ----
            {
                const int i = quad;
                const uint4* row = smu4 + buf * U4_PER_BUF + i * ROWU4;
                const int ig = ch * CH + i;
                float av[3];
                float se = 0.f;
#pragma unroll
                for (int jj = 0; jj < 3; jj++) {
                    if (jj < jn) {
                        const int j = g + 4 * jj;
                        const uint4 q0 = row[2 * j];
                        const uint4 q1 = row[2 * j + 1];
                        const __half2* ha = reinterpret_cast<const __half2*>(&q0);
                        const __half2* hb = reinterpret_cast<const __half2*>(&q1);
                        __half2 a2 = __float2half2_rn(0.f);
#pragma unroll
                        for (int m = 0; m < 4; m++) a2 = __hfma2(ha[m], us2[j * 8 + m], a2);
#pragma unroll
                        for (int m = 0; m < 4; m++) a2 = __hfma2(hb[m], us2[j * 8 + 4 + m], a2);
                        av[jj] = __expf(__low2float(a2) + __high2float(a2) +
                                        __ldg(&bias[ig * NC + j]));
                        se += av[jj];
                    }
                }
                se += __shfl_xor_sync(0xffffffffu, se, 1);
                se += __shfl_xor_sync(0xffffffffu, se, 2);
                const float inv = __fdividef(1.f, se);
#pragma unroll
                for (int jj = 0; jj < 3; jj++)
                    if (jj < jn) c_f[i * NC + g + 4 * jj] = av[jj] * inv;
            }
            __syncthreads();

            // ---- Phase B: weighted sum, lane-owns-jd (warp w: 8 i's) ----
            {
                const __half* hb0 = reinterpret_cast<const __half*>(
                    smu4 + buf * U4_PER_BUF + (w * 8) * ROWU4);
                const float* cb0 = c_f + (w * 8) * NC;
#pragma unroll
                for (int t = 0; t < 8; t++) {
                    const __half* hp = hb0 + t * ROWH;
                    const float*  cp = cb0 + t * NC;
#pragma unroll
                    for (int k = 0; k < 5; k++) {
                        const int jd = lane + 32 * k;
                        acc[k] = fmaf(cp[jd >> 4], __half2float(hp[jd]), acc[k]);
                    }
                }
            }
            __syncthreads();   // buf consumed; next iter may overwrite it
        }

        if (pass == 0) load_chunk(b, 0, 0, tid);   // prefetch pass-1 chunk 0

        // ---- reduce + squash ----
#pragma unroll
        for (int k = 0; k < 5; k++) sred[w * JD + lane + 32 * k] = acc[k];
        __syncthreads();
        if (tid < JD) {
            float s = 0.f;
#pragma unroll
            for (int w2 = 0; w2 < RT_WARPS; w2++) s += sred[w2 * JD + tid];
            s_sm[tid] = s;
        }
        __syncthreads();
        if (tid < NC) {
            float s2 = 0.f;
#pragma unroll
            for (int d = 0; d < DV; d++) { float v = s_sm[tid * DV + d]; s2 = fmaf(v, v, s2); }
            scale_sm[tid] = s2 / (1.0f + s2) * rsqrtf(s2);
        }
        __syncthreads();
        if (tid < JD) {
            const float v = scale_sm[tid >> 4] * s_sm[tid];
            if (pass == 0) u_f[tid] += v;                 // u = v0 + v1
            else           out[(size_t)b * JD + tid] = v; // final v2
        }
        __syncthreads();
        if (pass == 0 && tid < JD / 2)
            us2[tid] = __floats2half2_rn(u_f[2 * tid], u_f[2 * tid + 1]);
        __syncthreads();
    }
}

// ---------------------------------------------------------------------------
extern "C" void kernel_launch(void* const* d_in, const int* in_sizes, int n_in,
                              void* d_out, int out_size)
{
    const float* x    = (const float*)d_in[0];
    const float* W    = (const float*)d_in[1];
    const float* bias = (const float*)d_in[2];
    float* out        = (float*)d_out;

    cudaFuncSetAttribute(route_kernel,
                         cudaFuncAttributeMaxDynamicSharedMemorySize, SMH_BYTES);

    transpose_W<<<IC, 128>>>(W);
    hat_s0_kernel<<<dim3(HK_NCHUNK, HK_NBT), 256>>>(x, bias);
    route_kernel<<<Bn, RT_THREADS, SMH_BYTES>>>(bias, out);
}